// round 15
// baseline (speedup 1.0000x reference)
#include <cuda_runtime.h>
#include <math.h>
#include <stdint.h>

#define N_ROWS 131072
#define DIM    512
#define NGRP   4096
#define EPSV   1e-12f

// ---------------- scratch (static device arrays; no allocation allowed) ----------------
__device__ float g_wc    [3][DIM * DIM];           // tf32-rounded Wg*(1+2^-11), Wf*(1+2^-11), Wh
__device__ float g_num   [NGRP * DIM];             // segment sums: feats*exp(l)
__device__ float g_den   [NGRP * DIM];             // segment sums: exp(l)
__device__ float g_y     [NGRP * DIM];             // normalized aggregate (tf32-rounded)
__device__ int   g_counts [NGRP];
__device__ int   g_offsets[NGRP + 1];
__device__ int   g_cursor [NGRP];
__device__ int   g_perm   [N_ROWS];
__device__ int   g_gids   [N_ROWS];                // sorted group id per sorted row

// RZ-truncation compensation for un-prerounded A operand: E[trunc] = a*(1-2^-11)
#define COMP 1.00048828125f

// ====================== helpers ======================
__device__ __forceinline__ uint32_t smem_u32(const void* p) {
    uint32_t a;
    asm("{ .reg .u64 t; cvta.to.shared.u64 t, %1; cvt.u32.u64 %0, t; }" : "=r"(a) : "l"(p));
    return a;
}
__device__ __forceinline__ void cpa16(uint32_t dst, const void* src) {
    asm volatile("cp.async.cg.shared.global [%0], [%1], 16;" :: "r"(dst), "l"(src) : "memory");
}
__device__ __forceinline__ float tf32r(float x) {
    uint32_t u;
    asm("cvt.rna.tf32.f32 %0, %1;" : "=r"(u) : "f"(x));
    return __uint_as_float(u);
}
__device__ __forceinline__ void mma8(float* d, const uint32_t* a, uint32_t b0, uint32_t b1) {
    asm volatile(
        "mma.sync.aligned.m16n8k8.row.col.f32.tf32.tf32.f32 "
        "{%0,%1,%2,%3}, {%4,%5,%6,%7}, {%8,%9}, {%0,%1,%2,%3};"
        : "+f"(d[0]), "+f"(d[1]), "+f"(d[2]), "+f"(d[3])
        : "r"(a[0]), "r"(a[1]), "r"(a[2]), "r"(a[3]), "r"(b0), "r"(b1));
}

// ====================== GEMM tiling constants ======================
#define KC      32
#define CHUNKS  (DIM / KC)          // 16
#define SA      36                  // floats per smem row (KC + 4 pad)
#define ATF     (128 * SA)
#define STGF    (2 * ATF)           // A 128 rows + B 128 rows
// fused: 2 stages -> 73.9 KB/CTA -> 3 CTAs/SM
#define FSTG    2
#define SMEM_F  (FSTG * STGF * 4 + 512)
// gemm3: 3 stages; epilogue stages 128x132 tile (67.6 KB) in same smem
#define G3STG   3
#define SMEM_G3 (G3STG * STGF * 4)
#define EST     133                 // fused epilogue staging stride
#define OST     132                 // gemm3 output staging stride

// 128 rows x KC floats, contiguous rows (256 threads)
__device__ __forceinline__ void load_tile_A(uint32_t dst, const float* src, int k0, int t) {
    #pragma unroll
    for (int j = 0; j < 4; j++) {
        int idx = j * 256 + t;
        int row = idx >> 3, seg = idx & 7;
        cpa16(dst + row * (SA * 4) + seg * 16,
              src + (size_t)row * DIM + k0 + seg * 4);
    }
}
// 128 rows x KC floats, rows indirected through smem perm table (128 threads)
__device__ __forceinline__ void load_tile_Aperm128(uint32_t dst, const float* src,
                                                   const int* perm_s, int k0, int t) {
    #pragma unroll
    for (int j = 0; j < 8; j++) {
        int idx = j * 128 + t;
        int row = idx >> 3, seg = idx & 7;
        cpa16(dst + row * (SA * 4) + seg * 16,
              src + (size_t)perm_s[row] * DIM + k0 + seg * 4);
    }
}
// B tile: rows 0..63 = Wg[n0..], rows 64..127 = Wf[n0..] (128 threads)
__device__ __forceinline__ void load_tile_B2_128(uint32_t dst, const float* Wg, const float* Wf,
                                                 int n0, int k0, int t) {
    #pragma unroll
    for (int j = 0; j < 8; j++) {
        int idx = j * 128 + t;
        int row = idx >> 3, seg = idx & 7;
        const float* base = (row < 64) ? (Wg + (size_t)(n0 + row) * DIM)
                                       : (Wf + (size_t)(n0 + row - 64) * DIM);
        cpa16(dst + row * (SA * 4) + seg * 16, base + k0 + seg * 4);
    }
}

// ====================== fused dual-GEMM + softmax segment-reduce ======================
// grid (8, 1024): n0 = bx*64, m0 = by*128. A = x (raw fp32), rows via perm table.
// 128 threads, 4 warps, 2-stage pipeline, 3 CTAs/SM.
// Warp tile: M64(wr) x N64 of ONE matrix (wmat).
__global__ __launch_bounds__(128, 3) void gemm_fused(
    const float* __restrict__ x_, const float* __restrict__ bg_, const float* __restrict__ bf_)
{
    extern __shared__ float sm[];
    const uint32_t sb = smem_u32(sm);
    int* perm_s = (int*)(sm + FSTG * STGF);
    const int t = threadIdx.x;
    const int wid = t >> 5, lid = t & 31;
    const int g = lid >> 2, c = lid & 3;
    const int wr = wid & 1;            // M half (64 rows)
    const int wmat = wid >> 1;         // 0 = Wg/logits, 1 = Wf/feats

    const int n0 = blockIdx.x * 64;
    const int m0 = blockIdx.y * 128;
    const float* Wg = g_wc[0];
    const float* Wf = g_wc[1];

    perm_s[t] = g_perm[m0 + t];
    __syncthreads();

    float acc[4][8][4];
    #pragma unroll
    for (int mf = 0; mf < 4; mf++)
        #pragma unroll
        for (int nf = 0; nf < 8; nf++)
            #pragma unroll
            for (int q = 0; q < 4; q++) acc[mf][nf][q] = 0.f;

    // prologue: chunk 0 -> stage 0
    load_tile_Aperm128(sb, x_, perm_s, 0, t);
    load_tile_B2_128(sb + ATF * 4, Wg, Wf, n0, 0, t);
    asm volatile("cp.async.commit_group;" ::: "memory");

    for (int i = 0; i < CHUNKS; i++) {
        int s = i & 1;
        if (i + 1 < CHUNKS) {
            int s1 = (i + 1) & 1;
            load_tile_Aperm128(sb + s1 * STGF * 4, x_, perm_s, (i + 1) * KC, t);
            load_tile_B2_128(sb + s1 * STGF * 4 + ATF * 4, Wg, Wf, n0, (i + 1) * KC, t);
            asm volatile("cp.async.commit_group;" ::: "memory");
            asm volatile("cp.async.wait_group 1;" ::: "memory");
        } else {
            asm volatile("cp.async.wait_group 0;" ::: "memory");
        }
        __syncthreads();

        const float* As = sm + s * STGF + (wr * 64) * SA;
        const float* Bs = sm + s * STGF + ATF + (wmat * 64) * SA;
        #pragma unroll
        for (int kk = 0; kk < KC; kk += 8) {
            uint32_t a[4][4];
            #pragma unroll
            for (int mf = 0; mf < 4; mf++) {
                const float* ap = As + (mf * 16 + g) * SA + kk + c;
                a[mf][0] = __float_as_uint(ap[0]);
                a[mf][1] = __float_as_uint(ap[8 * SA]);
                a[mf][2] = __float_as_uint(ap[4]);
                a[mf][3] = __float_as_uint(ap[8 * SA + 4]);
            }
            #pragma unroll
            for (int nf = 0; nf < 8; nf++) {
                const float* bp = Bs + (nf * 8 + g) * SA + kk + c;
                uint32_t b0 = __float_as_uint(bp[0]);
                uint32_t b1 = __float_as_uint(bp[4]);
                #pragma unroll
                for (int mf = 0; mf < 4; mf++)
                    mma8(acc[mf][nf], a[mf], b0, b1);
            }
        }
        __syncthreads();   // stage s is free for the overwrite issued next iteration
    }

    // ---- epilogue: stage (l, f) transposed [col][row], stride EST ----
    float* sl = sm;
    float* sf = sm + 64 * EST;
    int* sgid = (int*)(sm + 2 * 64 * EST);
    sgid[t] = g_gids[m0 + t];
    float* sdst = wmat ? sf : sl;
    const float* bias = wmat ? bf_ : bg_;
    #pragma unroll
    for (int nf = 0; nf < 8; nf++) {
        int cb = nf * 8 + c * 2;
        float2 bv = *(const float2*)(bias + n0 + cb);
        #pragma unroll
        for (int mf = 0; mf < 4; mf++) {
            int r0 = wr * 64 + mf * 16 + g;
            sdst[cb * EST + r0]           = acc[mf][nf][0] + bv.x;
            sdst[(cb + 1) * EST + r0]     = acc[mf][nf][1] + bv.y;
            sdst[cb * EST + r0 + 8]       = acc[mf][nf][2] + bv.x;
            sdst[(cb + 1) * EST + r0 + 8] = acc[mf][nf][3] + bv.y;
        }
    }
    __syncthreads();

    // ---- segmented reduce over sorted rows; flush per group via atomics ----
    // 128 threads = 64 cols x 2 chunks of 64 rows
    {
        int col = t & 63, q = t >> 6;
        int gcol = n0 + col;
        int r = q * 64;
        int curg = sgid[r];
        float num = 0.f, den = 0.f;
        #pragma unroll 1
        for (int k = 0; k < 64; k++, r++) {
            int gg = sgid[r];
            float l = sl[col * EST + r];
            float f = sf[col * EST + r];
            float e = __expf(l);
            if (gg != curg) {
                atomicAdd(&g_num[(size_t)curg * DIM + gcol], num);
                atomicAdd(&g_den[(size_t)curg * DIM + gcol], den);
                num = 0.f; den = 0.f; curg = gg;
            }
            num += f * e;
            den += e;
        }
        atomicAdd(&g_num[(size_t)curg * DIM + gcol], num);
        atomicAdd(&g_den[(size_t)curg * DIM + gcol], den);
    }
}

// ====================== GEMM3 + gather: out[i,:] = (y @ Wh^T + bh)[jx[i],:] ======================
// grid (4, 32), 256 threads, CTA 128x128, 3-stage pipeline.
// Epilogue stages the group-tile to smem, then writes directly to out for every member row.
__global__ __launch_bounds__(256, 2) void gemm_mma3(const float* __restrict__ bias,
                                                    float* __restrict__ out)
{
    extern __shared__ float sm[];
    const uint32_t sb = smem_u32(sm);
    const int t = threadIdx.x;
    const int wid = t >> 5, lid = t & 31;
    const int g = lid >> 2, c = lid & 3;
    const int wr = wid & 3, wc = wid >> 2;

    const int m0 = blockIdx.y * 128, n0 = blockIdx.x * 128;
    const float* Ab = g_y + (size_t)m0 * DIM;
    const float* Wb = g_wc[2] + (size_t)n0 * DIM;

    float acc[2][8][4];
    #pragma unroll
    for (int mf = 0; mf < 2; mf++)
        #pragma unroll
        for (int nf = 0; nf < 8; nf++)
            #pragma unroll
            for (int q = 0; q < 4; q++) acc[mf][nf][q] = 0.f;

    #pragma unroll
    for (int cc = 0; cc < G3STG - 1; cc++) {
        load_tile_A(sb + cc * STGF * 4,           Ab, cc * KC, t);
        load_tile_A(sb + cc * STGF * 4 + ATF * 4, Wb, cc * KC, t);
        asm volatile("cp.async.commit_group;" ::: "memory");
    }

    for (int i = 0; i < CHUNKS; i++) {
        asm volatile("cp.async.wait_group 1;" ::: "memory");
        __syncthreads();
        int nxt = i + G3STG - 1;
        if (nxt < CHUNKS) {
            int s = nxt % G3STG;
            load_tile_A(sb + s * STGF * 4,           Ab, nxt * KC, t);
            load_tile_A(sb + s * STGF * 4 + ATF * 4, Wb, nxt * KC, t);
        }
        asm volatile("cp.async.commit_group;" ::: "memory");

        const float* As = sm + (i % G3STG) * STGF + (wr * 32) * SA;
        const float* Bs = sm + (i % G3STG) * STGF + ATF + (wc * 64) * SA;
        #pragma unroll
        for (int kk = 0; kk < KC; kk += 8) {
            uint32_t a[2][4];
            #pragma unroll
            for (int mf = 0; mf < 2; mf++) {
                const float* ap = As + (mf * 16 + g) * SA + kk + c;
                a[mf][0] = __float_as_uint(ap[0]);
                a[mf][1] = __float_as_uint(ap[8 * SA]);
                a[mf][2] = __float_as_uint(ap[4]);
                a[mf][3] = __float_as_uint(ap[8 * SA + 4]);
            }
            #pragma unroll
            for (int nf = 0; nf < 8; nf++) {
                const float* bp = Bs + (nf * 8 + g) * SA + kk + c;
                uint32_t bb0 = __float_as_uint(bp[0]);
                uint32_t bb1 = __float_as_uint(bp[4]);
                mma8(acc[0][nf], a[0], bb0, bb1);
                mma8(acc[1][nf], a[1], bb0, bb1);
            }
        }
    }
    __syncthreads();   // pipeline smem no longer needed

    // ---- stage out_group tile (bias added) to smem: st[group_row][col], stride OST ----
    float* st = sm;
    #pragma unroll
    for (int nf = 0; nf < 8; nf++) {
        int col = wc * 64 + nf * 8 + c * 2;
        float bv0 = bias[n0 + col], bv1 = bias[n0 + col + 1];
        #pragma unroll
        for (int mf = 0; mf < 2; mf++) {
            int r0 = wr * 32 + mf * 16 + g;
            st[r0 * OST + col]            = acc[mf][nf][0] + bv0;
            st[r0 * OST + col + 1]        = acc[mf][nf][1] + bv1;
            st[(r0 + 8) * OST + col]      = acc[mf][nf][2] + bv0;
            st[(r0 + 8) * OST + col + 1]  = acc[mf][nf][3] + bv1;
        }
    }
    __syncthreads();

    // ---- gather: for every member row of groups [m0, m0+128), write its 128-col slice ----
    {
        int base = g_offsets[m0];
        int cnt = g_offsets[m0 + 128] - base;
        for (int idx = t; idx < cnt * 32; idx += 256) {
            int r = base + (idx >> 5);
            int cs = idx & 31;
            int grow = g_gids[r] - m0;
            float4 v = *(const float4*)(st + grow * OST + cs * 4);
            *(float4*)(out + (size_t)g_perm[r] * DIM + n0 + cs * 4) = v;
        }
    }
}

// ---------------- small kernels ----------------
// merged: zero num/den/counts + W tf32 conversion (Wg/Wf scaled by COMP, Wh plain)
__global__ void conv_w_zero_k(const float4* __restrict__ Wg, const float4* __restrict__ Wf,
                              const float4* __restrict__ Wh) {
    int i = blockIdx.x * blockDim.x + threadIdx.x;
    const int per = DIM * DIM / 4;
    if (i < 3 * per) {
        int mat = i / per, j = i % per;
        const float4* src = (mat == 0) ? Wg : (mat == 1) ? Wf : Wh;
        float s = (mat == 2) ? 1.0f : COMP;
        float4 v = src[j];
        v.x = tf32r(v.x * s); v.y = tf32r(v.y * s);
        v.z = tf32r(v.z * s); v.w = tf32r(v.w * s);
        ((float4*)g_wc[mat])[j] = v;
    }
    if (i < NGRP * DIM / 4) {
        float4 z = make_float4(0.f, 0.f, 0.f, 0.f);
        ((float4*)g_num)[i] = z;
        ((float4*)g_den)[i] = z;
    }
    if (i < NGRP) g_counts[i] = 0;
}
__global__ void hist_k(const int* __restrict__ jx) {
    int i = blockIdx.x * blockDim.x + threadIdx.x;
    if (i < N_ROWS) atomicAdd(&g_counts[jx[i]], 1);
}
// shuffle-based exclusive scan over NGRP=4096 counts (1024 threads, 4 elems/thread)
__global__ void scan_k() {
    __shared__ int ws[32];
    int t = threadIdx.x;
    int lane = t & 31, w = t >> 5;
    int b = t * 4;
    int v0 = g_counts[b], v1 = g_counts[b + 1], v2 = g_counts[b + 2], v3 = g_counts[b + 3];
    int sum = v0 + v1 + v2 + v3;
    // warp inclusive scan of sum
    int s = sum;
    #pragma unroll
    for (int off = 1; off < 32; off <<= 1) {
        int n = __shfl_up_sync(0xFFFFFFFF, s, off);
        if (lane >= off) s += n;
    }
    if (lane == 31) ws[w] = s;
    __syncthreads();
    if (w == 0) {
        int x = ws[lane];
        #pragma unroll
        for (int off = 1; off < 32; off <<= 1) {
            int n = __shfl_up_sync(0xFFFFFFFF, x, off);
            if (lane >= off) x += n;
        }
        ws[lane] = x;
    }
    __syncthreads();
    int excl = s - sum + (w ? ws[w - 1] : 0);
    int o0 = excl, o1 = o0 + v0, o2 = o1 + v1, o3 = o2 + v2;
    g_offsets[b] = o0;     g_offsets[b + 1] = o1;
    g_offsets[b + 2] = o2; g_offsets[b + 3] = o3;
    g_cursor[b] = o0;      g_cursor[b + 1] = o1;
    g_cursor[b + 2] = o2;  g_cursor[b + 3] = o3;
    if (t == 1023) g_offsets[NGRP] = o3 + v3;
}
__global__ void scatter_k(const int* __restrict__ jx) {
    int i = blockIdx.x * blockDim.x + threadIdx.x;
    if (i < N_ROWS) {
        int g = jx[i];
        int pos = atomicAdd(&g_cursor[g], 1);
        g_perm[pos] = i;
        g_gids[pos] = g;
    }
}

// y = num / (den + eps), tf32-rounded for GEMM3
__global__ void norm_y_k() {
    int i = blockIdx.x * blockDim.x + threadIdx.x;
    if (i < NGRP * DIM) g_y[i] = tf32r(g_num[i] / (g_den[i] + EPSV));
}

extern "C" void kernel_launch(void* const* d_in, const int* in_sizes, int n_in,
                              void* d_out, int out_size) {
    const float* x  = (const float*)d_in[0];
    const float* Wf = (const float*)d_in[1];
    const float* bf = (const float*)d_in[2];
    const float* Wg = (const float*)d_in[3];
    const float* bg = (const float*)d_in[4];
    const float* Wh = (const float*)d_in[5];
    const float* bh = (const float*)d_in[6];
    const int*   jx = (const int*)d_in[7];
    float* out = (float*)d_out;
    (void)in_sizes; (void)n_in; (void)out_size;

    cudaFuncSetAttribute(gemm_fused, cudaFuncAttributeMaxDynamicSharedMemorySize, SMEM_F);
    cudaFuncSetAttribute(gemm_mma3,  cudaFuncAttributeMaxDynamicSharedMemorySize, SMEM_G3);

    // zero accumulators + W pre-conversion (merged), then counting sort of jx
    conv_w_zero_k<<<(NGRP * DIM / 4 + 255) / 256, 256>>>(
        (const float4*)Wg, (const float4*)Wf, (const float4*)Wh);
    hist_k<<<(N_ROWS + 255) / 256, 256>>>(jx);
    scan_k<<<1, 1024>>>();
    scatter_k<<<(N_ROWS + 255) / 256, 256>>>(jx);

    // fused dual GEMM + softmax segment-reduce (2-stage pipeline, 3 CTAs/SM)
    gemm_fused<<<dim3(8, N_ROWS / 128), 128, SMEM_F>>>(x, bg, bf);

    // y = num/(den+eps)
    norm_y_k<<<(NGRP * DIM + 255) / 256, 256>>>();

    // out_group = y @ Wh^T + bh, gathered directly into out
    gemm_mma3<<<dim3(4, NGRP / 128), 256, SMEM_G3>>>(bh, out);
}

// round 16
// speedup vs baseline: 1.1233x; 1.1233x over previous
#include <cuda_runtime.h>
#include <math.h>
#include <stdint.h>

#define N_ROWS 131072
#define DIM    512
#define NGRP   4096
#define EPSV   1e-12f

// ---------------- scratch (static device arrays; no allocation allowed) ----------------
__device__ float g_wc    [3][DIM * DIM];           // tf32-rounded Wg*(1+2^-11), Wf*(1+2^-11), Wh
__device__ float g_num   [NGRP * DIM];             // segment sums: feats*exp(l)
__device__ float g_den   [NGRP * DIM];             // segment sums: exp(l)
__device__ float g_y     [NGRP * DIM];             // normalized aggregate (tf32-rounded)
__device__ float g_outg  [NGRP * DIM];             // out_group = y @ Wh^T + bh
__device__ int   g_counts [NGRP];
__device__ int   g_offsets[NGRP + 1];
__device__ int   g_cursor [NGRP];
__device__ int   g_perm   [N_ROWS];
__device__ int   g_gids   [N_ROWS];                // sorted group id per sorted row

// RZ-truncation compensation for un-prerounded A operand: E[trunc] = a*(1-2^-11)
#define COMP 1.00048828125f

// ====================== helpers ======================
__device__ __forceinline__ uint32_t smem_u32(const void* p) {
    uint32_t a;
    asm("{ .reg .u64 t; cvta.to.shared.u64 t, %1; cvt.u32.u64 %0, t; }" : "=r"(a) : "l"(p));
    return a;
}
__device__ __forceinline__ void cpa16(uint32_t dst, const void* src) {
    asm volatile("cp.async.cg.shared.global [%0], [%1], 16;" :: "r"(dst), "l"(src) : "memory");
}
__device__ __forceinline__ float tf32r(float x) {
    uint32_t u;
    asm("cvt.rna.tf32.f32 %0, %1;" : "=r"(u) : "f"(x));
    return __uint_as_float(u);
}
__device__ __forceinline__ void mma8(float* d, const uint32_t* a, uint32_t b0, uint32_t b1) {
    asm volatile(
        "mma.sync.aligned.m16n8k8.row.col.f32.tf32.tf32.f32 "
        "{%0,%1,%2,%3}, {%4,%5,%6,%7}, {%8,%9}, {%0,%1,%2,%3};"
        : "+f"(d[0]), "+f"(d[1]), "+f"(d[2]), "+f"(d[3])
        : "r"(a[0]), "r"(a[1]), "r"(a[2]), "r"(a[3]), "r"(b0), "r"(b1));
}

// ====================== GEMM tiling constants ======================
#define KC      32
#define CHUNKS  (DIM / KC)          // 16
#define SA      36                  // floats per smem row (KC + 4 pad)
#define ATF     (128 * SA)
#define STGF    (2 * ATF)           // A 128 rows + B 128 rows
// fused: 2 stages -> 73.9 KB/CTA -> 3 CTAs/SM
#define FSTG    2
#define SMEM_F  (FSTG * STGF * 4 + 512)
// gemm3: 3 stages
#define G3STG   3
#define SMEM_G3 (G3STG * STGF * 4)
#define EST     133                 // epilogue staging stride

// 128 rows x KC floats, contiguous rows (256 threads)
__device__ __forceinline__ void load_tile_A(uint32_t dst, const float* src, int k0, int t) {
    #pragma unroll
    for (int j = 0; j < 4; j++) {
        int idx = j * 256 + t;
        int row = idx >> 3, seg = idx & 7;
        cpa16(dst + row * (SA * 4) + seg * 16,
              src + (size_t)row * DIM + k0 + seg * 4);
    }
}
// 128 rows x KC floats, rows indirected through smem perm table (128 threads)
__device__ __forceinline__ void load_tile_Aperm128(uint32_t dst, const float* src,
                                                   const int* perm_s, int k0, int t) {
    #pragma unroll
    for (int j = 0; j < 8; j++) {
        int idx = j * 128 + t;
        int row = idx >> 3, seg = idx & 7;
        cpa16(dst + row * (SA * 4) + seg * 16,
              src + (size_t)perm_s[row] * DIM + k0 + seg * 4);
    }
}
// B tile: rows 0..63 = Wg[n0..], rows 64..127 = Wf[n0..] (128 threads)
__device__ __forceinline__ void load_tile_B2_128(uint32_t dst, const float* Wg, const float* Wf,
                                                 int n0, int k0, int t) {
    #pragma unroll
    for (int j = 0; j < 8; j++) {
        int idx = j * 128 + t;
        int row = idx >> 3, seg = idx & 7;
        const float* base = (row < 64) ? (Wg + (size_t)(n0 + row) * DIM)
                                       : (Wf + (size_t)(n0 + row - 64) * DIM);
        cpa16(dst + row * (SA * 4) + seg * 16, base + k0 + seg * 4);
    }
}

// ====================== fused dual-GEMM + softmax segment-reduce ======================
// grid (8, 1024): n0 = bx*64, m0 = by*128. A = x (raw fp32), rows via perm table.
// 128 threads, 4 warps, 2-stage pipeline, 3 CTAs/SM.
// Warp tile: M64(wr) x N64 of ONE matrix (wmat).
__global__ __launch_bounds__(128, 3) void gemm_fused(
    const float* __restrict__ x_, const float* __restrict__ bg_, const float* __restrict__ bf_)
{
    extern __shared__ float sm[];
    const uint32_t sb = smem_u32(sm);
    int* perm_s = (int*)(sm + FSTG * STGF);
    const int t = threadIdx.x;
    const int wid = t >> 5, lid = t & 31;
    const int g = lid >> 2, c = lid & 3;
    const int wr = wid & 1;            // M half (64 rows)
    const int wmat = wid >> 1;         // 0 = Wg/logits, 1 = Wf/feats

    const int n0 = blockIdx.x * 64;
    const int m0 = blockIdx.y * 128;
    const float* Wg = g_wc[0];
    const float* Wf = g_wc[1];

    perm_s[t] = g_perm[m0 + t];
    __syncthreads();

    float acc[4][8][4];
    #pragma unroll
    for (int mf = 0; mf < 4; mf++)
        #pragma unroll
        for (int nf = 0; nf < 8; nf++)
            #pragma unroll
            for (int q = 0; q < 4; q++) acc[mf][nf][q] = 0.f;

    // prologue: chunk 0 -> stage 0
    load_tile_Aperm128(sb, x_, perm_s, 0, t);
    load_tile_B2_128(sb + ATF * 4, Wg, Wf, n0, 0, t);
    asm volatile("cp.async.commit_group;" ::: "memory");

    for (int i = 0; i < CHUNKS; i++) {
        int s = i & 1;
        if (i + 1 < CHUNKS) {
            int s1 = (i + 1) & 1;
            load_tile_Aperm128(sb + s1 * STGF * 4, x_, perm_s, (i + 1) * KC, t);
            load_tile_B2_128(sb + s1 * STGF * 4 + ATF * 4, Wg, Wf, n0, (i + 1) * KC, t);
            asm volatile("cp.async.commit_group;" ::: "memory");
            asm volatile("cp.async.wait_group 1;" ::: "memory");
        } else {
            asm volatile("cp.async.wait_group 0;" ::: "memory");
        }
        __syncthreads();

        const float* As = sm + s * STGF + (wr * 64) * SA;
        const float* Bs = sm + s * STGF + ATF + (wmat * 64) * SA;
        #pragma unroll
        for (int kk = 0; kk < KC; kk += 8) {
            uint32_t a[4][4];
            #pragma unroll
            for (int mf = 0; mf < 4; mf++) {
                const float* ap = As + (mf * 16 + g) * SA + kk + c;
                a[mf][0] = __float_as_uint(ap[0]);
                a[mf][1] = __float_as_uint(ap[8 * SA]);
                a[mf][2] = __float_as_uint(ap[4]);
                a[mf][3] = __float_as_uint(ap[8 * SA + 4]);
            }
            #pragma unroll
            for (int nf = 0; nf < 8; nf++) {
                const float* bp = Bs + (nf * 8 + g) * SA + kk + c;
                uint32_t b0 = __float_as_uint(bp[0]);
                uint32_t b1 = __float_as_uint(bp[4]);
                #pragma unroll
                for (int mf = 0; mf < 4; mf++)
                    mma8(acc[mf][nf], a[mf], b0, b1);
            }
        }
        __syncthreads();   // stage s is free for the overwrite issued next iteration
    }

    // ---- epilogue: stage (l, f) transposed [col][row], stride EST ----
    float* sl = sm;
    float* sf = sm + 64 * EST;
    int* sgid = (int*)(sm + 2 * 64 * EST);
    sgid[t] = g_gids[m0 + t];
    float* sdst = wmat ? sf : sl;
    const float* bias = wmat ? bf_ : bg_;
    #pragma unroll
    for (int nf = 0; nf < 8; nf++) {
        int cb = nf * 8 + c * 2;
        float2 bv = *(const float2*)(bias + n0 + cb);
        #pragma unroll
        for (int mf = 0; mf < 4; mf++) {
            int r0 = wr * 64 + mf * 16 + g;
            sdst[cb * EST + r0]           = acc[mf][nf][0] + bv.x;
            sdst[(cb + 1) * EST + r0]     = acc[mf][nf][1] + bv.y;
            sdst[cb * EST + r0 + 8]       = acc[mf][nf][2] + bv.x;
            sdst[(cb + 1) * EST + r0 + 8] = acc[mf][nf][3] + bv.y;
        }
    }
    __syncthreads();

    // ---- segmented reduce over sorted rows; flush per group via atomics ----
    // 128 threads = 64 cols x 2 chunks of 64 rows
    {
        int col = t & 63, q = t >> 6;
        int gcol = n0 + col;
        int r = q * 64;
        int curg = sgid[r];
        float num = 0.f, den = 0.f;
        #pragma unroll 1
        for (int k = 0; k < 64; k++, r++) {
            int gg = sgid[r];
            float l = sl[col * EST + r];
            float f = sf[col * EST + r];
            float e = __expf(l);
            if (gg != curg) {
                atomicAdd(&g_num[(size_t)curg * DIM + gcol], num);
                atomicAdd(&g_den[(size_t)curg * DIM + gcol], den);
                num = 0.f; den = 0.f; curg = gg;
            }
            num += f * e;
            den += e;
        }
        atomicAdd(&g_num[(size_t)curg * DIM + gcol], num);
        atomicAdd(&g_den[(size_t)curg * DIM + gcol], den);
    }
}

// ====================== GEMM3: out_group = y @ Wh^T + bh ======================
// grid (4, 32), 256 threads, CTA 128x128, 3-stage pipeline
__global__ __launch_bounds__(256, 2) void gemm_mma3(const float* __restrict__ bias)
{
    extern __shared__ float sm[];
    const uint32_t sb = smem_u32(sm);
    const int t = threadIdx.x;
    const int wid = t >> 5, lid = t & 31;
    const int g = lid >> 2, c = lid & 3;
    const int wr = wid & 3, wc = wid >> 2;

    const int m0 = blockIdx.y * 128, n0 = blockIdx.x * 128;
    const float* Ab = g_y + (size_t)m0 * DIM;
    const float* Wb = g_wc[2] + (size_t)n0 * DIM;
    float* C = g_outg;

    float acc[2][8][4];
    #pragma unroll
    for (int mf = 0; mf < 2; mf++)
        #pragma unroll
        for (int nf = 0; nf < 8; nf++)
            #pragma unroll
            for (int q = 0; q < 4; q++) acc[mf][nf][q] = 0.f;

    #pragma unroll
    for (int cc = 0; cc < G3STG - 1; cc++) {
        load_tile_A(sb + cc * STGF * 4,           Ab, cc * KC, t);
        load_tile_A(sb + cc * STGF * 4 + ATF * 4, Wb, cc * KC, t);
        asm volatile("cp.async.commit_group;" ::: "memory");
    }

    for (int i = 0; i < CHUNKS; i++) {
        asm volatile("cp.async.wait_group 1;" ::: "memory");
        __syncthreads();
        int nxt = i + G3STG - 1;
        if (nxt < CHUNKS) {
            int s = nxt % G3STG;
            load_tile_A(sb + s * STGF * 4,           Ab, nxt * KC, t);
            load_tile_A(sb + s * STGF * 4 + ATF * 4, Wb, nxt * KC, t);
        }
        asm volatile("cp.async.commit_group;" ::: "memory");

        const float* As = sm + (i % G3STG) * STGF + (wr * 32) * SA;
        const float* Bs = sm + (i % G3STG) * STGF + ATF + (wc * 64) * SA;
        #pragma unroll
        for (int kk = 0; kk < KC; kk += 8) {
            uint32_t a[2][4];
            #pragma unroll
            for (int mf = 0; mf < 2; mf++) {
                const float* ap = As + (mf * 16 + g) * SA + kk + c;
                a[mf][0] = __float_as_uint(ap[0]);
                a[mf][1] = __float_as_uint(ap[8 * SA]);
                a[mf][2] = __float_as_uint(ap[4]);
                a[mf][3] = __float_as_uint(ap[8 * SA + 4]);
            }
            #pragma unroll
            for (int nf = 0; nf < 8; nf++) {
                const float* bp = Bs + (nf * 8 + g) * SA + kk + c;
                uint32_t bb0 = __float_as_uint(bp[0]);
                uint32_t bb1 = __float_as_uint(bp[4]);
                mma8(acc[0][nf], a[0], bb0, bb1);
                mma8(acc[1][nf], a[1], bb0, bb1);
            }
        }
    }

    const int rowb = m0 + wr * 32 + g;
    const int colb = n0 + wc * 64 + c * 2;
    #pragma unroll
    for (int nf = 0; nf < 8; nf++) {
        int col = colb + nf * 8;
        float bv0 = bias[col], bv1 = bias[col + 1];
        #pragma unroll
        for (int mf = 0; mf < 2; mf++) {
            int r0 = rowb + mf * 16;
            float2 v;
            v.x = acc[mf][nf][0] + bv0; v.y = acc[mf][nf][1] + bv1;
            *(float2*)(C + (size_t)r0 * DIM + col) = v;
            v.x = acc[mf][nf][2] + bv0; v.y = acc[mf][nf][3] + bv1;
            *(float2*)(C + (size_t)(r0 + 8) * DIM + col) = v;
        }
    }
}

// ---------------- small kernels ----------------
// merged: zero num/den/counts + W tf32 conversion (Wg/Wf scaled by COMP, Wh plain)
__global__ void conv_w_zero_k(const float4* __restrict__ Wg, const float4* __restrict__ Wf,
                              const float4* __restrict__ Wh) {
    int i = blockIdx.x * blockDim.x + threadIdx.x;
    const int per = DIM * DIM / 4;
    if (i < 3 * per) {
        int mat = i / per, j = i % per;
        const float4* src = (mat == 0) ? Wg : (mat == 1) ? Wf : Wh;
        float s = (mat == 2) ? 1.0f : COMP;
        float4 v = src[j];
        v.x = tf32r(v.x * s); v.y = tf32r(v.y * s);
        v.z = tf32r(v.z * s); v.w = tf32r(v.w * s);
        ((float4*)g_wc[mat])[j] = v;
    }
    if (i < NGRP * DIM / 4) {
        float4 z = make_float4(0.f, 0.f, 0.f, 0.f);
        ((float4*)g_num)[i] = z;
        ((float4*)g_den)[i] = z;
    }
    if (i < NGRP) g_counts[i] = 0;
}
__global__ void hist_k(const int* __restrict__ jx) {
    int i = blockIdx.x * blockDim.x + threadIdx.x;
    if (i < N_ROWS) atomicAdd(&g_counts[jx[i]], 1);
}
// shuffle-based exclusive scan over NGRP=4096 counts (1024 threads, 4 elems/thread)
__global__ void scan_k() {
    __shared__ int ws[32];
    int t = threadIdx.x;
    int lane = t & 31, w = t >> 5;
    int b = t * 4;
    int v0 = g_counts[b], v1 = g_counts[b + 1], v2 = g_counts[b + 2], v3 = g_counts[b + 3];
    int sum = v0 + v1 + v2 + v3;
    // warp inclusive scan of sum
    int s = sum;
    #pragma unroll
    for (int off = 1; off < 32; off <<= 1) {
        int n = __shfl_up_sync(0xFFFFFFFF, s, off);
        if (lane >= off) s += n;
    }
    if (lane == 31) ws[w] = s;
    __syncthreads();
    if (w == 0) {
        int x = ws[lane];
        #pragma unroll
        for (int off = 1; off < 32; off <<= 1) {
            int n = __shfl_up_sync(0xFFFFFFFF, x, off);
            if (lane >= off) x += n;
        }
        ws[lane] = x;
    }
    __syncthreads();
    int excl = s - sum + (w ? ws[w - 1] : 0);
    int o0 = excl, o1 = o0 + v0, o2 = o1 + v1, o3 = o2 + v2;
    g_offsets[b] = o0;     g_offsets[b + 1] = o1;
    g_offsets[b + 2] = o2; g_offsets[b + 3] = o3;
    g_cursor[b] = o0;      g_cursor[b + 1] = o1;
    g_cursor[b + 2] = o2;  g_cursor[b + 3] = o3;
    if (t == 1023) g_offsets[NGRP] = o3 + v3;
}
__global__ void scatter_k(const int* __restrict__ jx) {
    int i = blockIdx.x * blockDim.x + threadIdx.x;
    if (i < N_ROWS) {
        int g = jx[i];
        int pos = atomicAdd(&g_cursor[g], 1);
        g_perm[pos] = i;
        g_gids[pos] = g;
    }
}

// y = num / (den + eps), tf32-rounded for GEMM3
__global__ void norm_y_k() {
    int i = blockIdx.x * blockDim.x + threadIdx.x;
    if (i < NGRP * DIM) g_y[i] = tf32r(g_num[i] / (g_den[i] + EPSV));
}

// out[i,:] = outg[jx[i],:]
__global__ void gather_k(const int* __restrict__ jx, float4* __restrict__ out) {
    int idx = blockIdx.x * blockDim.x + threadIdx.x;
    if (idx < N_ROWS * (DIM / 4)) {
        int i = idx >> 7;
        int c = idx & 127;
        out[idx] = ((const float4*)g_outg)[((size_t)jx[i] << 7) + c];
    }
}

extern "C" void kernel_launch(void* const* d_in, const int* in_sizes, int n_in,
                              void* d_out, int out_size) {
    const float* x  = (const float*)d_in[0];
    const float* Wf = (const float*)d_in[1];
    const float* bf = (const float*)d_in[2];
    const float* Wg = (const float*)d_in[3];
    const float* bg = (const float*)d_in[4];
    const float* Wh = (const float*)d_in[5];
    const float* bh = (const float*)d_in[6];
    const int*   jx = (const int*)d_in[7];
    float* out = (float*)d_out;
    (void)in_sizes; (void)n_in; (void)out_size;

    cudaFuncSetAttribute(gemm_fused, cudaFuncAttributeMaxDynamicSharedMemorySize, SMEM_F);
    cudaFuncSetAttribute(gemm_mma3,  cudaFuncAttributeMaxDynamicSharedMemorySize, SMEM_G3);

    // zero accumulators + W pre-conversion (merged), then counting sort of jx
    conv_w_zero_k<<<(NGRP * DIM / 4 + 255) / 256, 256>>>(
        (const float4*)Wg, (const float4*)Wf, (const float4*)Wh);
    hist_k<<<(N_ROWS + 255) / 256, 256>>>(jx);
    scan_k<<<1, 1024>>>();
    scatter_k<<<(N_ROWS + 255) / 256, 256>>>(jx);

    // fused dual GEMM + softmax segment-reduce (2-stage pipeline, 3 CTAs/SM)
    gemm_fused<<<dim3(8, N_ROWS / 128), 128, SMEM_F>>>(x, bg, bf);

    // y = num/(den+eps)
    norm_y_k<<<(NGRP * DIM + 255) / 256, 256>>>();

    // out_group = y @ Wh^T + bh
    gemm_mma3<<<dim3(4, NGRP / 128), 256, SMEM_G3>>>(bh);

    // out = out_group[jx]
    gather_k<<<(N_ROWS * (DIM / 4) + 255) / 256, 256>>>(jx, (float4*)out);
}

// round 17
// speedup vs baseline: 1.1239x; 1.0006x over previous
#include <cuda_runtime.h>
#include <math.h>
#include <stdint.h>

#define N_ROWS 131072
#define DIM    512
#define NGRP   4096
#define EPSV   1e-12f

// ---------------- scratch (static device arrays; no allocation allowed) ----------------
__device__ float g_wc    [3][DIM * DIM];           // tf32-rounded Wg*(1+2^-11), Wf*(1+2^-11), Wh
__device__ float g_num   [NGRP * DIM];             // segment sums: feats*exp(l)
__device__ float g_den   [NGRP * DIM];             // segment sums: exp(l)
__device__ float g_y     [NGRP * DIM];             // normalized aggregate (tf32-rounded)
__device__ float g_outg  [NGRP * DIM];             // out_group = y @ Wh^T + bh
__device__ int   g_counts [NGRP];
__device__ int   g_offsets[NGRP + 1];
__device__ int   g_cursor [NGRP];
__device__ int   g_perm   [N_ROWS];
__device__ int   g_gids   [N_ROWS];                // sorted group id per sorted row

// RZ-truncation compensation for un-prerounded A operand: E[trunc] = a*(1-2^-11)
#define COMP 1.00048828125f

// ====================== helpers ======================
__device__ __forceinline__ uint32_t smem_u32(const void* p) {
    uint32_t a;
    asm("{ .reg .u64 t; cvta.to.shared.u64 t, %1; cvt.u32.u64 %0, t; }" : "=r"(a) : "l"(p));
    return a;
}
__device__ __forceinline__ void cpa16(uint32_t dst, const void* src) {
    asm volatile("cp.async.cg.shared.global [%0], [%1], 16;" :: "r"(dst), "l"(src) : "memory");
}
__device__ __forceinline__ float tf32r(float x) {
    uint32_t u;
    asm("cvt.rna.tf32.f32 %0, %1;" : "=r"(u) : "f"(x));
    return __uint_as_float(u);
}
__device__ __forceinline__ void mma8(float* d, const uint32_t* a, uint32_t b0, uint32_t b1) {
    asm volatile(
        "mma.sync.aligned.m16n8k8.row.col.f32.tf32.tf32.f32 "
        "{%0,%1,%2,%3}, {%4,%5,%6,%7}, {%8,%9}, {%0,%1,%2,%3};"
        : "+f"(d[0]), "+f"(d[1]), "+f"(d[2]), "+f"(d[3])
        : "r"(a[0]), "r"(a[1]), "r"(a[2]), "r"(a[3]), "r"(b0), "r"(b1));
}

// ====================== GEMM tiling constants ======================
#define KC      32
#define CHUNKS  (DIM / KC)          // 16
#define SA      36                  // floats per smem row (KC + 4 pad)
#define ATF     (128 * SA)
#define STGF    (2 * ATF)           // A 128 rows + B 128 rows
// fused: 2 stages -> 73.9 KB/CTA -> 3 CTAs/SM
#define FSTG    2
#define SMEM_F  (FSTG * STGF * 4 + 512)
// gemm3: 3 stages
#define G3STG   3
#define SMEM_G3 (G3STG * STGF * 4)
#define EST     133                 // epilogue staging stride

// 128 rows x KC floats, contiguous rows (256 threads)
__device__ __forceinline__ void load_tile_A(uint32_t dst, const float* src, int k0, int t) {
    #pragma unroll
    for (int j = 0; j < 4; j++) {
        int idx = j * 256 + t;
        int row = idx >> 3, seg = idx & 7;
        cpa16(dst + row * (SA * 4) + seg * 16,
              src + (size_t)row * DIM + k0 + seg * 4);
    }
}
// 128 rows x KC floats, rows indirected through smem perm table (128 threads)
__device__ __forceinline__ void load_tile_Aperm128(uint32_t dst, const float* src,
                                                   const int* perm_s, int k0, int t) {
    #pragma unroll
    for (int j = 0; j < 8; j++) {
        int idx = j * 128 + t;
        int row = idx >> 3, seg = idx & 7;
        cpa16(dst + row * (SA * 4) + seg * 16,
              src + (size_t)perm_s[row] * DIM + k0 + seg * 4);
    }
}
// B tile: rows 0..63 = Wg[n0..], rows 64..127 = Wf[n0..] (128 threads)
__device__ __forceinline__ void load_tile_B2_128(uint32_t dst, const float* Wg, const float* Wf,
                                                 int n0, int k0, int t) {
    #pragma unroll
    for (int j = 0; j < 8; j++) {
        int idx = j * 128 + t;
        int row = idx >> 3, seg = idx & 7;
        const float* base = (row < 64) ? (Wg + (size_t)(n0 + row) * DIM)
                                       : (Wf + (size_t)(n0 + row - 64) * DIM);
        cpa16(dst + row * (SA * 4) + seg * 16, base + k0 + seg * 4);
    }
}

// ====================== fused dual-GEMM + softmax segment-reduce ======================
// grid (8, 1024): n0 = bx*64, m0 = by*128. A = x (raw fp32), rows via perm table.
// 128 threads, 4 warps, 2-stage pipeline, 3 CTAs/SM.
// Warp tile: M64(wr) x N64 of ONE matrix (wmat).
__global__ __launch_bounds__(128, 3) void gemm_fused(
    const float* __restrict__ x_, const float* __restrict__ bg_, const float* __restrict__ bf_)
{
    extern __shared__ float sm[];
    const uint32_t sb = smem_u32(sm);
    int* perm_s = (int*)(sm + FSTG * STGF);
    const int t = threadIdx.x;
    const int wid = t >> 5, lid = t & 31;
    const int g = lid >> 2, c = lid & 3;
    const int wr = wid & 1;            // M half (64 rows)
    const int wmat = wid >> 1;         // 0 = Wg/logits, 1 = Wf/feats

    const int n0 = blockIdx.x * 64;
    const int m0 = blockIdx.y * 128;
    const float* Wg = g_wc[0];
    const float* Wf = g_wc[1];

    perm_s[t] = g_perm[m0 + t];
    const int my_gid = g_gids[m0 + t];     // prefetched for the epilogue
    __syncthreads();

    float acc[4][8][4];
    #pragma unroll
    for (int mf = 0; mf < 4; mf++)
        #pragma unroll
        for (int nf = 0; nf < 8; nf++)
            #pragma unroll
            for (int q = 0; q < 4; q++) acc[mf][nf][q] = 0.f;

    // prologue: chunk 0 -> stage 0
    load_tile_Aperm128(sb, x_, perm_s, 0, t);
    load_tile_B2_128(sb + ATF * 4, Wg, Wf, n0, 0, t);
    asm volatile("cp.async.commit_group;" ::: "memory");

    for (int i = 0; i < CHUNKS; i++) {
        int s = i & 1;
        if (i + 1 < CHUNKS) {
            int s1 = (i + 1) & 1;
            load_tile_Aperm128(sb + s1 * STGF * 4, x_, perm_s, (i + 1) * KC, t);
            load_tile_B2_128(sb + s1 * STGF * 4 + ATF * 4, Wg, Wf, n0, (i + 1) * KC, t);
            asm volatile("cp.async.commit_group;" ::: "memory");
            asm volatile("cp.async.wait_group 1;" ::: "memory");
        } else {
            asm volatile("cp.async.wait_group 0;" ::: "memory");
        }
        __syncthreads();

        const float* As = sm + s * STGF + (wr * 64) * SA;
        const float* Bs = sm + s * STGF + ATF + (wmat * 64) * SA;
        #pragma unroll
        for (int kk = 0; kk < KC; kk += 8) {
            uint32_t a[4][4];
            #pragma unroll
            for (int mf = 0; mf < 4; mf++) {
                const float* ap = As + (mf * 16 + g) * SA + kk + c;
                a[mf][0] = __float_as_uint(ap[0]);
                a[mf][1] = __float_as_uint(ap[8 * SA]);
                a[mf][2] = __float_as_uint(ap[4]);
                a[mf][3] = __float_as_uint(ap[8 * SA + 4]);
            }
            #pragma unroll
            for (int nf = 0; nf < 8; nf++) {
                const float* bp = Bs + (nf * 8 + g) * SA + kk + c;
                uint32_t b0 = __float_as_uint(bp[0]);
                uint32_t b1 = __float_as_uint(bp[4]);
                #pragma unroll
                for (int mf = 0; mf < 4; mf++)
                    mma8(acc[mf][nf], a[mf], b0, b1);
            }
        }
        __syncthreads();   // stage s is free for the overwrite issued next iteration
    }

    // ---- epilogue: stage (l, f) transposed [col][row], stride EST ----
    float* sl = sm;
    float* sf = sm + 64 * EST;
    int* sgid = (int*)(sm + 2 * 64 * EST);
    sgid[t] = my_gid;
    float* sdst = wmat ? sf : sl;
    const float* bias = wmat ? bf_ : bg_;
    #pragma unroll
    for (int nf = 0; nf < 8; nf++) {
        int cb = nf * 8 + c * 2;
        float2 bv = *(const float2*)(bias + n0 + cb);
        #pragma unroll
        for (int mf = 0; mf < 4; mf++) {
            int r0 = wr * 64 + mf * 16 + g;
            sdst[cb * EST + r0]           = acc[mf][nf][0] + bv.x;
            sdst[(cb + 1) * EST + r0]     = acc[mf][nf][1] + bv.y;
            sdst[cb * EST + r0 + 8]       = acc[mf][nf][2] + bv.x;
            sdst[(cb + 1) * EST + r0 + 8] = acc[mf][nf][3] + bv.y;
        }
    }
    __syncthreads();

    // ---- segmented reduce over sorted rows; flush per group via atomics ----
    // 128 threads = 64 cols x 2 chunks of 64 rows
    {
        int col = t & 63, q = t >> 6;
        int gcol = n0 + col;
        int r = q * 64;
        int curg = sgid[r];
        float num = 0.f, den = 0.f;
        #pragma unroll 1
        for (int k = 0; k < 64; k++, r++) {
            int gg = sgid[r];
            float l = sl[col * EST + r];
            float f = sf[col * EST + r];
            float e = __expf(l);
            if (gg != curg) {
                atomicAdd(&g_num[(size_t)curg * DIM + gcol], num);
                atomicAdd(&g_den[(size_t)curg * DIM + gcol], den);
                num = 0.f; den = 0.f; curg = gg;
            }
            num += f * e;
            den += e;
        }
        atomicAdd(&g_num[(size_t)curg * DIM + gcol], num);
        atomicAdd(&g_den[(size_t)curg * DIM + gcol], den);
    }
}

// ====================== GEMM3: out_group = y @ Wh^T + bh ======================
// grid (4, 32), 256 threads, CTA 128x128, 3-stage pipeline
__global__ __launch_bounds__(256, 2) void gemm_mma3(const float* __restrict__ bias)
{
    extern __shared__ float sm[];
    const uint32_t sb = smem_u32(sm);
    const int t = threadIdx.x;
    const int wid = t >> 5, lid = t & 31;
    const int g = lid >> 2, c = lid & 3;
    const int wr = wid & 3, wc = wid >> 2;

    const int m0 = blockIdx.y * 128, n0 = blockIdx.x * 128;
    const float* Ab = g_y + (size_t)m0 * DIM;
    const float* Wb = g_wc[2] + (size_t)n0 * DIM;
    float* C = g_outg;

    float acc[2][8][4];
    #pragma unroll
    for (int mf = 0; mf < 2; mf++)
        #pragma unroll
        for (int nf = 0; nf < 8; nf++)
            #pragma unroll
            for (int q = 0; q < 4; q++) acc[mf][nf][q] = 0.f;

    #pragma unroll
    for (int cc = 0; cc < G3STG - 1; cc++) {
        load_tile_A(sb + cc * STGF * 4,           Ab, cc * KC, t);
        load_tile_A(sb + cc * STGF * 4 + ATF * 4, Wb, cc * KC, t);
        asm volatile("cp.async.commit_group;" ::: "memory");
    }

    for (int i = 0; i < CHUNKS; i++) {
        asm volatile("cp.async.wait_group 1;" ::: "memory");
        __syncthreads();
        int nxt = i + G3STG - 1;
        if (nxt < CHUNKS) {
            int s = nxt % G3STG;
            load_tile_A(sb + s * STGF * 4,           Ab, nxt * KC, t);
            load_tile_A(sb + s * STGF * 4 + ATF * 4, Wb, nxt * KC, t);
        }
        asm volatile("cp.async.commit_group;" ::: "memory");

        const float* As = sm + (i % G3STG) * STGF + (wr * 32) * SA;
        const float* Bs = sm + (i % G3STG) * STGF + ATF + (wc * 64) * SA;
        #pragma unroll
        for (int kk = 0; kk < KC; kk += 8) {
            uint32_t a[2][4];
            #pragma unroll
            for (int mf = 0; mf < 2; mf++) {
                const float* ap = As + (mf * 16 + g) * SA + kk + c;
                a[mf][0] = __float_as_uint(ap[0]);
                a[mf][1] = __float_as_uint(ap[8 * SA]);
                a[mf][2] = __float_as_uint(ap[4]);
                a[mf][3] = __float_as_uint(ap[8 * SA + 4]);
            }
            #pragma unroll
            for (int nf = 0; nf < 8; nf++) {
                const float* bp = Bs + (nf * 8 + g) * SA + kk + c;
                uint32_t bb0 = __float_as_uint(bp[0]);
                uint32_t bb1 = __float_as_uint(bp[4]);
                mma8(acc[0][nf], a[0], bb0, bb1);
                mma8(acc[1][nf], a[1], bb0, bb1);
            }
        }
    }

    const int rowb = m0 + wr * 32 + g;
    const int colb = n0 + wc * 64 + c * 2;
    #pragma unroll
    for (int nf = 0; nf < 8; nf++) {
        int col = colb + nf * 8;
        float bv0 = bias[col], bv1 = bias[col + 1];
        #pragma unroll
        for (int mf = 0; mf < 2; mf++) {
            int r0 = rowb + mf * 16;
            float2 v;
            v.x = acc[mf][nf][0] + bv0; v.y = acc[mf][nf][1] + bv1;
            *(float2*)(C + (size_t)r0 * DIM + col) = v;
            v.x = acc[mf][nf][2] + bv0; v.y = acc[mf][nf][3] + bv1;
            *(float2*)(C + (size_t)(r0 + 8) * DIM + col) = v;
        }
    }
}

// ---------------- small kernels ----------------
// merged: zero num/den/counts + W tf32 conversion (Wg/Wf scaled by COMP, Wh plain)
__global__ void conv_w_zero_k(const float4* __restrict__ Wg, const float4* __restrict__ Wf,
                              const float4* __restrict__ Wh) {
    int i = blockIdx.x * blockDim.x + threadIdx.x;
    const int per = DIM * DIM / 4;
    if (i < 3 * per) {
        int mat = i / per, j = i % per;
        const float4* src = (mat == 0) ? Wg : (mat == 1) ? Wf : Wh;
        float s = (mat == 2) ? 1.0f : COMP;
        float4 v = src[j];
        v.x = tf32r(v.x * s); v.y = tf32r(v.y * s);
        v.z = tf32r(v.z * s); v.w = tf32r(v.w * s);
        ((float4*)g_wc[mat])[j] = v;
    }
    if (i < NGRP * DIM / 4) {
        float4 z = make_float4(0.f, 0.f, 0.f, 0.f);
        ((float4*)g_num)[i] = z;
        ((float4*)g_den)[i] = z;
    }
    if (i < NGRP) g_counts[i] = 0;
}
__global__ void hist_k(const int* __restrict__ jx) {
    int i = blockIdx.x * blockDim.x + threadIdx.x;
    if (i < N_ROWS) atomicAdd(&g_counts[jx[i]], 1);
}
// shuffle-based exclusive scan over NGRP=4096 counts (1024 threads, 4 elems/thread)
__global__ void scan_k() {
    __shared__ int ws[32];
    int t = threadIdx.x;
    int lane = t & 31, w = t >> 5;
    int b = t * 4;
    int v0 = g_counts[b], v1 = g_counts[b + 1], v2 = g_counts[b + 2], v3 = g_counts[b + 3];
    int sum = v0 + v1 + v2 + v3;
    int s = sum;
    #pragma unroll
    for (int off = 1; off < 32; off <<= 1) {
        int n = __shfl_up_sync(0xFFFFFFFF, s, off);
        if (lane >= off) s += n;
    }
    if (lane == 31) ws[w] = s;
    __syncthreads();
    if (w == 0) {
        int x = ws[lane];
        #pragma unroll
        for (int off = 1; off < 32; off <<= 1) {
            int n = __shfl_up_sync(0xFFFFFFFF, x, off);
            if (lane >= off) x += n;
        }
        ws[lane] = x;
    }
    __syncthreads();
    int excl = s - sum + (w ? ws[w - 1] : 0);
    int o0 = excl, o1 = o0 + v0, o2 = o1 + v1, o3 = o2 + v2;
    g_offsets[b] = o0;     g_offsets[b + 1] = o1;
    g_offsets[b + 2] = o2; g_offsets[b + 3] = o3;
    g_cursor[b] = o0;      g_cursor[b + 1] = o1;
    g_cursor[b + 2] = o2;  g_cursor[b + 3] = o3;
    if (t == 1023) g_offsets[NGRP] = o3 + v3;
}
__global__ void scatter_k(const int* __restrict__ jx) {
    int i = blockIdx.x * blockDim.x + threadIdx.x;
    if (i < N_ROWS) {
        int g = jx[i];
        int pos = atomicAdd(&g_cursor[g], 1);
        g_perm[pos] = i;
        g_gids[pos] = g;
    }
}

// y = num / (den + eps), tf32-rounded for GEMM3 (vectorized)
__global__ void norm_y_k() {
    int i = blockIdx.x * blockDim.x + threadIdx.x;
    if (i < NGRP * DIM / 4) {
        float4 n = ((const float4*)g_num)[i];
        float4 d = ((const float4*)g_den)[i];
        float4 y;
        y.x = tf32r(n.x / (d.x + EPSV));
        y.y = tf32r(n.y / (d.y + EPSV));
        y.z = tf32r(n.z / (d.z + EPSV));
        y.w = tf32r(n.w / (d.w + EPSV));
        ((float4*)g_y)[i] = y;
    }
}

// out[i,:] = outg[jx[i],:] — 2 float4s per thread, one jx read each
__global__ void gather_k(const int* __restrict__ jx, float4* __restrict__ out) {
    int idx = blockIdx.x * blockDim.x + threadIdx.x;   // over N_ROWS * 64
    if (idx < N_ROWS * (DIM / 8)) {
        int i = idx >> 6;
        int c = (idx & 63) * 2;
        const float4* src = (const float4*)g_outg + ((size_t)jx[i] << 7) + c;
        float4 v0 = src[0];
        float4 v1 = src[1];
        float4* dst = out + ((size_t)i << 7) + c;
        dst[0] = v0;
        dst[1] = v1;
    }
}

extern "C" void kernel_launch(void* const* d_in, const int* in_sizes, int n_in,
                              void* d_out, int out_size) {
    const float* x  = (const float*)d_in[0];
    const float* Wf = (const float*)d_in[1];
    const float* bf = (const float*)d_in[2];
    const float* Wg = (const float*)d_in[3];
    const float* bg = (const float*)d_in[4];
    const float* Wh = (const float*)d_in[5];
    const float* bh = (const float*)d_in[6];
    const int*   jx = (const int*)d_in[7];
    float* out = (float*)d_out;
    (void)in_sizes; (void)n_in; (void)out_size;

    cudaFuncSetAttribute(gemm_fused, cudaFuncAttributeMaxDynamicSharedMemorySize, SMEM_F);
    cudaFuncSetAttribute(gemm_mma3,  cudaFuncAttributeMaxDynamicSharedMemorySize, SMEM_G3);

    // zero accumulators + W pre-conversion (merged), then counting sort of jx
    conv_w_zero_k<<<(NGRP * DIM / 4 + 255) / 256, 256>>>(
        (const float4*)Wg, (const float4*)Wf, (const float4*)Wh);
    hist_k<<<(N_ROWS + 255) / 256, 256>>>(jx);
    scan_k<<<1, 1024>>>();
    scatter_k<<<(N_ROWS + 255) / 256, 256>>>(jx);

    // fused dual GEMM + softmax segment-reduce (2-stage pipeline, 3 CTAs/SM)
    gemm_fused<<<dim3(8, N_ROWS / 128), 128, SMEM_F>>>(x, bg, bf);

    // y = num/(den+eps)
    norm_y_k<<<(NGRP * DIM / 4 + 255) / 256, 256>>>();

    // out_group = y @ Wh^T + bh
    gemm_mma3<<<dim3(4, NGRP / 128), 256, SMEM_G3>>>(bh);

    // out = out_group[jx]
    gather_k<<<(N_ROWS * (DIM / 8) + 255) / 256, 256>>>(jx, (float4*)out);
}